// round 14
// baseline (speedup 1.0000x reference)
#include <cuda_runtime.h>
#include <cuda_fp16.h>

// SpatialTransformer: out[b,c,d,h,w] = trilinear_sample(src[b,c], (w,h,d)+flow[b,:,d,h,w])
// align_corners=True normalization cancels; padding_mode='zeros'.
//
// R14: R12 config (half2 tile, 3 blocks x 512 = 48 warps, regs 40 — R13 proved
// 4-block/regs-32 regresses) with halo RH=4: tile 41x25x17 half2 = 69.7KB,
// 3x69.7 = 209KB < 228KB carveout. Fallback probability per voxel drops
// 0.8% -> 0.019%, so warps executing BOTH paths drop 23% -> 0.6%, removing the
// divergence tax R12 still paid. HFMA2 zy-blend kept (rel_err 4.4e-4 < 1e-3).

#define Dz 160
#define Hy 192
#define Wx 160
#define Bn 2
#define HW (Hy * Wx)            // 30720
#define DHW (Dz * Hy * Wx)      // 4915200

#define RH 4                    // halo radius
#define TX 32
#define TY 16
#define TZ 8
#define EX (TX + 2 * RH + 1)    // 41
#define EY (TY + 2 * RH + 1)    // 25
#define EZ (TZ + 2 * RH + 1)    // 17
#define NROWS (EY * EZ)         // 425
#define ESZ (EX * NROWS)        // 17425
#define SMEM_BYTES (ESZ * (int)sizeof(__half2))  // 69700

#define NTHREADS 512
#define NWARPS (NTHREADS / 32)  // 16

__device__ __forceinline__ void fallback_gather(
    const float* c0, const float* c1,
    int x0, int y0, int z0,
    float fx, float fy, float fz,
    float& acc0, float& acc1)
{
    int x1 = x0 + 1, y1 = y0 + 1, z1 = z0 + 1;
    float wx0 = (x0 >= 0 && x0 < Wx) ? (1.0f - fx) : 0.0f;
    float wx1 = (x1 >= 0 && x1 < Wx) ? fx          : 0.0f;
    float wy0 = (y0 >= 0 && y0 < Hy) ? (1.0f - fy) : 0.0f;
    float wy1 = (y1 >= 0 && y1 < Hy) ? fy          : 0.0f;
    float wz0 = (z0 >= 0 && z0 < Dz) ? (1.0f - fz) : 0.0f;
    float wz1 = (z1 >= 0 && z1 < Dz) ? fz          : 0.0f;

    int x0c = min(max(x0, 0), Wx - 1);
    int x1c = min(max(x1, 0), Wx - 1);
    int y0c = min(max(y0, 0), Hy - 1);
    int y1c = min(max(y1, 0), Hy - 1);
    int z0c = min(max(z0, 0), Dz - 1);
    int z1c = min(max(z1, 0), Dz - 1);

    int zy00 = z0c * HW + y0c * Wx;
    int zy01 = z0c * HW + y1c * Wx;
    int zy10 = z1c * HW + y0c * Wx;
    int zy11 = z1c * HW + y1c * Wx;

    float w00 = wz0 * wy0, w01 = wz0 * wy1;
    float w10 = wz1 * wy0, w11 = wz1 * wy1;
    float w000 = w00 * wx0, w001 = w00 * wx1;
    float w010 = w01 * wx0, w011 = w01 * wx1;
    float w100 = w10 * wx0, w101 = w10 * wx1;
    float w110 = w11 * wx0, w111 = w11 * wx1;

    acc0  = w000 * __ldg(c0 + zy00 + x0c) + w001 * __ldg(c0 + zy00 + x1c);
    acc0 += w010 * __ldg(c0 + zy01 + x0c) + w011 * __ldg(c0 + zy01 + x1c);
    acc0 += w100 * __ldg(c0 + zy10 + x0c) + w101 * __ldg(c0 + zy10 + x1c);
    acc0 += w110 * __ldg(c0 + zy11 + x0c) + w111 * __ldg(c0 + zy11 + x1c);

    acc1  = w000 * __ldg(c1 + zy00 + x0c) + w001 * __ldg(c1 + zy00 + x1c);
    acc1 += w010 * __ldg(c1 + zy01 + x0c) + w011 * __ldg(c1 + zy01 + x1c);
    acc1 += w100 * __ldg(c1 + zy10 + x0c) + w101 * __ldg(c1 + zy10 + x1c);
    acc1 += w110 * __ldg(c1 + zy11 + x0c) + w111 * __ldg(c1 + zy11 + x1c);
}

template <bool INTERIOR>
__device__ __forceinline__ void gather_loop(
    const __half2* __restrict__ tile,
    const float* __restrict__ c0, const float* __restrict__ c1,
    const float* __restrict__ fb, float* __restrict__ ob,
    int w, int h, int bz, int x_org, int y_org, int z_org)
{
    int s_base = ((bz * TZ) * Hy + h) * Wx + w;

    #pragma unroll
    for (int kz = 0; kz < TZ; kz++) {
        int d = bz * TZ + kz;
        int s = s_base + kz * HW;

        float x = (float)w + __ldg(fb + s);
        float y = (float)h + __ldg(fb + s + DHW);
        float z = (float)d + __ldg(fb + s + 2 * DHW);

        float x0f = floorf(x), y0f = floorf(y), z0f = floorf(z);
        float fx = x - x0f, fy = y - y0f, fz = z - z0f;
        int x0 = (int)x0f, y0 = (int)y0f, z0 = (int)z0f;

        int lx = x0 - x_org;
        int ly = y0 - y_org;
        int lz = z0 - z_org;

        float acc0, acc1;
        if ((unsigned)lx < (unsigned)(EX - 1) &&
            (unsigned)ly < (unsigned)(EY - 1) &&
            (unsigned)lz < (unsigned)(EZ - 1)) {
            float wx0, wx1, wy0, wy1, wz0, wz1;
            if (INTERIOR) {
                wx0 = 1.0f - fx; wx1 = fx;
                wy0 = 1.0f - fy; wy1 = fy;
                wz0 = 1.0f - fz; wz1 = fz;
            } else {
                wx0 = (x0 >= 0 && x0 < Wx)         ? (1.0f - fx) : 0.0f;
                wx1 = (x0 + 1 >= 0 && x0 + 1 < Wx) ? fx          : 0.0f;
                wy0 = (y0 >= 0 && y0 < Hy)         ? (1.0f - fy) : 0.0f;
                wy1 = (y0 + 1 >= 0 && y0 + 1 < Hy) ? fy          : 0.0f;
                wz0 = (z0 >= 0 && z0 < Dz)         ? (1.0f - fz) : 0.0f;
                wz1 = (z0 + 1 >= 0 && z0 + 1 < Dz) ? fz          : 0.0f;
            }

            // zy-plane weights, broadcast to both halves (channels).
            __half2 hw00 = __float2half2_rn(wz0 * wy0);
            __half2 hw01 = __float2half2_rn(wz0 * wy1);
            __half2 hw10 = __float2half2_rn(wz1 * wy0);
            __half2 hw11 = __float2half2_rn(wz1 * wy1);

            const __half2* t00 = tile + (lz * EY + ly) * EX + lx;
            const __half2* t10 = t00 + EY * EX;

            // lo/hi = sum over 4 zy-corners, both channels per HFMA2.
            __half2 lo = __hmul2(hw00, t00[0]);
            lo = __hfma2(hw01, t00[EX],     lo);
            lo = __hfma2(hw10, t10[0],      lo);
            lo = __hfma2(hw11, t10[EX],     lo);
            __half2 hi = __hmul2(hw00, t00[1]);
            hi = __hfma2(hw01, t00[EX + 1], hi);
            hi = __hfma2(hw10, t10[1],      hi);
            hi = __hfma2(hw11, t10[EX + 1], hi);

            float2 flo = __half22float2(lo);
            float2 fhi = __half22float2(hi);

            acc0 = wx0 * flo.x + wx1 * fhi.x;
            acc1 = wx0 * flo.y + wx1 * fhi.y;
        } else {
            fallback_gather(c0, c1, x0, y0, z0, fx, fy, fz, acc0, acc1);
        }

        ob[s] = acc0;
        ob[DHW + s] = acc1;
    }
}

__global__ __launch_bounds__(NTHREADS, 3) void warp3d_tiled(
    const float* __restrict__ src,
    const float* __restrict__ flow,
    float* __restrict__ out)
{
    extern __shared__ __half2 tile[];

    int bx = blockIdx.x;            // 0..4
    int by = blockIdx.y;            // 0..11
    int bzb = blockIdx.z;           // 0..39
    int b  = bzb / (Dz / TZ);
    int bz = bzb % (Dz / TZ);

    int x_org = bx * TX - RH;
    int y_org = by * TY - RH;
    int z_org = bz * TZ - RH;

    const float* c0 = src + (size_t)b * 2 * DHW;
    const float* c1 = c0 + DHW;

    int lane = threadIdx.x & 31;
    int warp = threadIdx.x >> 5;    // 0..15

    // ---- Fill: each warp copies whole (ez,ey) rows, coalesced strips ----
    for (int r = warp; r < NROWS; r += NWARPS) {
        int ey = r % EY;
        int ez = r / EY;
        int gy = min(max(y_org + ey, 0), Hy - 1);
        int gz = min(max(z_org + ez, 0), Dz - 1);
        const float* r0 = c0 + (gz * Hy + gy) * Wx;
        const float* r1 = c1 + (gz * Hy + gy) * Wx;
        __half2* trow = tile + r * EX;

        int gx0 = min(max(x_org + lane, 0), Wx - 1);
        trow[lane] = __floats2half2_rn(__ldg(r0 + gx0), __ldg(r1 + gx0));
        int ex = lane + 32;
        if (ex < EX) {
            int gx1 = min(max(x_org + ex, 0), Wx - 1);
            trow[ex] = __floats2half2_rn(__ldg(r0 + gx1), __ldg(r1 + gx1));
        }
    }
    __syncthreads();

    int w = bx * TX + lane;
    int h = by * TY + warp;
    const float* fb = flow + (size_t)b * 3 * DHW;
    float* ob = out + (size_t)b * 2 * DHW;

    bool interior = (x_org >= 0) && (x_org + EX <= Wx) &&
                    (y_org >= 0) && (y_org + EY <= Hy) &&
                    (z_org >= 0) && (z_org + EZ <= Dz);

    if (interior)
        gather_loop<true>(tile, c0, c1, fb, ob, w, h, bz, x_org, y_org, z_org);
    else
        gather_loop<false>(tile, c0, c1, fb, ob, w, h, bz, x_org, y_org, z_org);
}

extern "C" void kernel_launch(void* const* d_in, const int* in_sizes, int n_in,
                              void* d_out, int out_size) {
    const float* src  = (const float*)d_in[0];
    const float* flow = (const float*)d_in[1];
    float* out = (float*)d_out;

    cudaFuncSetAttribute(warp3d_tiled,
                         cudaFuncAttributeMaxDynamicSharedMemorySize, SMEM_BYTES);

    dim3 grid(Wx / TX, Hy / TY, (Dz / TZ) * Bn);
    warp3d_tiled<<<grid, NTHREADS, SMEM_BYTES>>>(src, flow, out);
}

// round 15
// speedup vs baseline: 1.2785x; 1.2785x over previous
#include <cuda_runtime.h>
#include <cuda_fp16.h>

// SpatialTransformer: out[b,c,d,h,w] = trilinear_sample(src[b,c], (w,h,d)+flow[b,:,d,h,w])
// align_corners=True normalization cancels; padding_mode='zeros'.
//
// R15: R12 config restored (the proven best: half2 tile 53.8KB, RH=3,
// 3 blocks x 512 = 48 warps; R13/R14 showed occ-up, halo-up both regress)
// + hot-path ALU trims:
//  - local-frame coords: lx = floor((lane+RH)+flowx) directly; global coords
//    reconstructed only on cold edge/fallback paths; (float)d becomes the
//    compile-time constant (kz+RH).
//  - interior x-blend in lerp form (2 ops instead of 3).
// HFMA2 zy-blend kept. |flow|>3 (~0.8%) -> exact fp32 global-path fallback.

#define Dz 160
#define Hy 192
#define Wx 160
#define Bn 2
#define HW (Hy * Wx)            // 30720
#define DHW (Dz * Hy * Wx)      // 4915200

#define RH 3                    // halo radius
#define TX 32
#define TY 16
#define TZ 8
#define EX (TX + 2 * RH + 1)    // 39
#define EY (TY + 2 * RH + 1)    // 23
#define EZ (TZ + 2 * RH + 1)    // 15
#define NROWS (EY * EZ)         // 345
#define ESZ (EX * NROWS)        // 13455
#define SMEM_BYTES (ESZ * (int)sizeof(__half2))  // 53820

#define NTHREADS 512
#define NWARPS (NTHREADS / 32)  // 16

__device__ __forceinline__ void fallback_gather(
    const float* c0, const float* c1,
    int x0, int y0, int z0,
    float fx, float fy, float fz,
    float& acc0, float& acc1)
{
    int x1 = x0 + 1, y1 = y0 + 1, z1 = z0 + 1;
    float wx0 = (x0 >= 0 && x0 < Wx) ? (1.0f - fx) : 0.0f;
    float wx1 = (x1 >= 0 && x1 < Wx) ? fx          : 0.0f;
    float wy0 = (y0 >= 0 && y0 < Hy) ? (1.0f - fy) : 0.0f;
    float wy1 = (y1 >= 0 && y1 < Hy) ? fy          : 0.0f;
    float wz0 = (z0 >= 0 && z0 < Dz) ? (1.0f - fz) : 0.0f;
    float wz1 = (z1 >= 0 && z1 < Dz) ? fz          : 0.0f;

    int x0c = min(max(x0, 0), Wx - 1);
    int x1c = min(max(x1, 0), Wx - 1);
    int y0c = min(max(y0, 0), Hy - 1);
    int y1c = min(max(y1, 0), Hy - 1);
    int z0c = min(max(z0, 0), Dz - 1);
    int z1c = min(max(z1, 0), Dz - 1);

    int zy00 = z0c * HW + y0c * Wx;
    int zy01 = z0c * HW + y1c * Wx;
    int zy10 = z1c * HW + y0c * Wx;
    int zy11 = z1c * HW + y1c * Wx;

    float w00 = wz0 * wy0, w01 = wz0 * wy1;
    float w10 = wz1 * wy0, w11 = wz1 * wy1;
    float w000 = w00 * wx0, w001 = w00 * wx1;
    float w010 = w01 * wx0, w011 = w01 * wx1;
    float w100 = w10 * wx0, w101 = w10 * wx1;
    float w110 = w11 * wx0, w111 = w11 * wx1;

    acc0  = w000 * __ldg(c0 + zy00 + x0c) + w001 * __ldg(c0 + zy00 + x1c);
    acc0 += w010 * __ldg(c0 + zy01 + x0c) + w011 * __ldg(c0 + zy01 + x1c);
    acc0 += w100 * __ldg(c0 + zy10 + x0c) + w101 * __ldg(c0 + zy10 + x1c);
    acc0 += w110 * __ldg(c0 + zy11 + x0c) + w111 * __ldg(c0 + zy11 + x1c);

    acc1  = w000 * __ldg(c1 + zy00 + x0c) + w001 * __ldg(c1 + zy00 + x1c);
    acc1 += w010 * __ldg(c1 + zy01 + x0c) + w011 * __ldg(c1 + zy01 + x1c);
    acc1 += w100 * __ldg(c1 + zy10 + x0c) + w101 * __ldg(c1 + zy10 + x1c);
    acc1 += w110 * __ldg(c1 + zy11 + x0c) + w111 * __ldg(c1 + zy11 + x1c);
}

template <bool INTERIOR>
__device__ __forceinline__ void gather_loop(
    const __half2* __restrict__ tile,
    const float* __restrict__ c0, const float* __restrict__ c1,
    const float* __restrict__ fb, float* __restrict__ ob,
    int lane, int warp, int bz, int x_org, int y_org, int z_org)
{
    int w = x_org + RH + lane;      // == bx*TX + lane
    int h = y_org + RH + warp;      // == by*TY + warp
    int s_base = ((bz * TZ) * Hy + h) * Wx + w;

    // Local-frame base offsets (constant per thread).
    float xbase = (float)(lane + RH);
    float ybase = (float)(warp + RH);

    #pragma unroll
    for (int kz = 0; kz < TZ; kz++) {
        int s = s_base + kz * HW;

        // Local-frame sample position: tile coords, not volume coords.
        float xl = xbase + __ldg(fb + s);
        float yl = ybase + __ldg(fb + s + DHW);
        float zl = (float)(kz + RH) + __ldg(fb + s + 2 * DHW);

        float lxf = floorf(xl), lyf = floorf(yl), lzf = floorf(zl);
        float fx = xl - lxf, fy = yl - lyf, fz = zl - lzf;
        int lx = (int)lxf, ly = (int)lyf, lz = (int)lzf;

        float acc0, acc1;
        if ((unsigned)lx < (unsigned)(EX - 1) &&
            (unsigned)ly < (unsigned)(EY - 1) &&
            (unsigned)lz < (unsigned)(EZ - 1)) {
            float wy0, wy1, wz0, wz1;
            float wx0 = 0.0f, wx1 = 0.0f;   // used by edge path only
            if (INTERIOR) {
                wy0 = 1.0f - fy; wy1 = fy;
                wz0 = 1.0f - fz; wz1 = fz;
            } else {
                int x0 = lx + x_org, y0 = ly + y_org, z0 = lz + z_org;
                wx0 = (x0 >= 0 && x0 < Wx)         ? (1.0f - fx) : 0.0f;
                wx1 = (x0 + 1 >= 0 && x0 + 1 < Wx) ? fx          : 0.0f;
                wy0 = (y0 >= 0 && y0 < Hy)         ? (1.0f - fy) : 0.0f;
                wy1 = (y0 + 1 >= 0 && y0 + 1 < Hy) ? fy          : 0.0f;
                wz0 = (z0 >= 0 && z0 < Dz)         ? (1.0f - fz) : 0.0f;
                wz1 = (z0 + 1 >= 0 && z0 + 1 < Dz) ? fz          : 0.0f;
            }

            // zy-plane weights, broadcast to both halves (channels).
            __half2 hw00 = __float2half2_rn(wz0 * wy0);
            __half2 hw01 = __float2half2_rn(wz0 * wy1);
            __half2 hw10 = __float2half2_rn(wz1 * wy0);
            __half2 hw11 = __float2half2_rn(wz1 * wy1);

            const __half2* t00 = tile + (lz * EY + ly) * EX + lx;
            const __half2* t10 = t00 + EY * EX;

            // lo/hi = sum over 4 zy-corners, both channels per HFMA2.
            __half2 lo = __hmul2(hw00, t00[0]);
            lo = __hfma2(hw01, t00[EX],     lo);
            lo = __hfma2(hw10, t10[0],      lo);
            lo = __hfma2(hw11, t10[EX],     lo);
            __half2 hi = __hmul2(hw00, t00[1]);
            hi = __hfma2(hw01, t00[EX + 1], hi);
            hi = __hfma2(hw10, t10[1],      hi);
            hi = __hfma2(hw11, t10[EX + 1], hi);

            float2 flo = __half22float2(lo);
            float2 fhi = __half22float2(hi);

            if (INTERIOR) {
                // wx0 = 1-fx, wx1 = fx -> lerp form (2 ops per channel).
                acc0 = fmaf(fx, fhi.x - flo.x, flo.x);
                acc1 = fmaf(fx, fhi.y - flo.y, flo.y);
            } else {
                acc0 = wx0 * flo.x + wx1 * fhi.x;
                acc1 = wx0 * flo.y + wx1 * fhi.y;
            }
        } else {
            fallback_gather(c0, c1, lx + x_org, ly + y_org, lz + z_org,
                            fx, fy, fz, acc0, acc1);
        }

        ob[s] = acc0;
        ob[DHW + s] = acc1;
    }
}

__global__ __launch_bounds__(NTHREADS, 3) void warp3d_tiled(
    const float* __restrict__ src,
    const float* __restrict__ flow,
    float* __restrict__ out)
{
    extern __shared__ __half2 tile[];

    int bx = blockIdx.x;            // 0..4
    int by = blockIdx.y;            // 0..11
    int bzb = blockIdx.z;           // 0..39
    int b  = bzb / (Dz / TZ);
    int bz = bzb % (Dz / TZ);

    int x_org = bx * TX - RH;
    int y_org = by * TY - RH;
    int z_org = bz * TZ - RH;

    const float* c0 = src + (size_t)b * 2 * DHW;
    const float* c1 = c0 + DHW;

    int lane = threadIdx.x & 31;
    int warp = threadIdx.x >> 5;    // 0..15

    // ---- Fill: each warp copies whole (ez,ey) rows, coalesced strips ----
    for (int r = warp; r < NROWS; r += NWARPS) {
        int ey = r % EY;
        int ez = r / EY;
        int gy = min(max(y_org + ey, 0), Hy - 1);
        int gz = min(max(z_org + ez, 0), Dz - 1);
        const float* r0 = c0 + (gz * Hy + gy) * Wx;
        const float* r1 = c1 + (gz * Hy + gy) * Wx;
        __half2* trow = tile + r * EX;

        int gx0 = min(max(x_org + lane, 0), Wx - 1);
        trow[lane] = __floats2half2_rn(__ldg(r0 + gx0), __ldg(r1 + gx0));
        int ex = lane + 32;
        if (ex < EX) {
            int gx1 = min(max(x_org + ex, 0), Wx - 1);
            trow[ex] = __floats2half2_rn(__ldg(r0 + gx1), __ldg(r1 + gx1));
        }
    }
    __syncthreads();

    const float* fb = flow + (size_t)b * 3 * DHW;
    float* ob = out + (size_t)b * 2 * DHW;

    bool interior = (x_org >= 0) && (x_org + EX <= Wx) &&
                    (y_org >= 0) && (y_org + EY <= Hy) &&
                    (z_org >= 0) && (z_org + EZ <= Dz);

    if (interior)
        gather_loop<true>(tile, c0, c1, fb, ob, lane, warp, bz, x_org, y_org, z_org);
    else
        gather_loop<false>(tile, c0, c1, fb, ob, lane, warp, bz, x_org, y_org, z_org);
}

extern "C" void kernel_launch(void* const* d_in, const int* in_sizes, int n_in,
                              void* d_out, int out_size) {
    const float* src  = (const float*)d_in[0];
    const float* flow = (const float*)d_in[1];
    float* out = (float*)d_out;

    cudaFuncSetAttribute(warp3d_tiled,
                         cudaFuncAttributeMaxDynamicSharedMemorySize, SMEM_BYTES);

    dim3 grid(Wx / TX, Hy / TY, (Dz / TZ) * Bn);
    warp3d_tiled<<<grid, NTHREADS, SMEM_BYTES>>>(src, flow, out);
}